// round 12
// baseline (speedup 1.0000x reference)
#include <cuda_runtime.h>
#include <cuda_bf16.h>
#include <math.h>

// ============================================================================
// Sinkhorn divergence (geomloss 'sinkhorn', p=2, blur=0.05, scaling=0.9).
//
// Round-5: Round-4 traffic-halving design + vectorized (LDG.128) tile loads
// to keep LSU issue 4x below the DRAM budget (512 -> 128 warp-LDGs/tile).
//  - C_yx never stored/read: gt comes from a fused column-LSE over C_xy.
//  - C_xx/C_yy symmetric: only upper-triangle 128x128 tiles built & read.
//  - smem tile stride 129 -> conflict-free row AND column access.
//  - exact 2-pass LSE per tile (max pass, then plain-add sum pass).
// Per-step traffic: ~533 MB vs 1024 MB in the 11347us baseline.
// ============================================================================

#define NPTS 4096
#define DDIM 64
#define NB   4
#define TS   128
#define NST  (NPTS / TS)               // 32 stripes
#define NUPPER (NST * (NST + 1) / 2)   // 528 upper tiles

// 12 matrices (xy, xx, yy per batch) x 64 MB = 768 MB
__device__ float g_C[(size_t)12 * NPTS * NPTS];
// partial (max,sum) per output row per stripe: [b][out][row][stripe]
// out: 0=f_ba(xy rows) 1=g_ab(xy cols) 2=f_aa(xx) 3=g_bb(yy)
__device__ float2 g_part[(size_t)NB * 4 * NPTS * NST];
// potentials ping-pong: [buf][b][{f_ba,g_ab,f_aa,g_bb}][NPTS]
__device__ float g_pot[2][NB][4][NPTS];
__device__ float g_potF[NB][4][NPTS];
__device__ float g_norm[2][NB][NPTS];

__device__ __forceinline__ float ex2f(float x) {
    float r;
    asm("ex2.approx.ftz.f32 %0, %1;" : "=f"(r) : "f"(x));
    return r;
}

// ---------------------------------------------------------------------------
__global__ void __launch_bounds__(256) norm_kernel(const float* __restrict__ x,
                                                   const float* __restrict__ y) {
    int t = blockIdx.x * 256 + threadIdx.x;
    int i = t & (NPTS - 1);
    int b = (t >> 12) & 3;
    int which = t >> 14;
    const float* p = (which ? y : x) + (size_t)b * DDIM * NPTS + i;
    float s = 0.f;
#pragma unroll
    for (int c = 0; c < DDIM; ++c) {
        float v = p[(size_t)c * NPTS];
        s = fmaf(v, v, s);
    }
    g_norm[which][b][i] = s;
}

// ---------------------------------------------------------------------------
// Cost matrices: mat 0: C(x,y); mat 1: C(x,x); mat 2: C(y,y).
// For mat>0 only upper 128-tiles (si<=sj) are written. grid=(64,64,12).
// ---------------------------------------------------------------------------
__global__ void __launch_bounds__(256) cost_kernel(const float* __restrict__ x,
                                                   const float* __restrict__ y) {
    const int which = blockIdx.z % 3;
    const int b = blockIdx.z / 3;
    if (which > 0 && (blockIdx.x >> 1) > (blockIdx.y >> 1)) return;  // upper only

    const float* u = (which == 2) ? y : x;
    const float* v = (which == 1) ? x : y;
    const float* nu = g_norm[(which == 2) ? 1 : 0][b];
    const float* nv = g_norm[(which == 1) ? 0 : 1][b];
    u += (size_t)b * DDIM * NPTS;
    v += (size_t)b * DDIM * NPTS;

    const int I = blockIdx.x * 64;
    const int J = blockIdx.y * 64;

    __shared__ float Us[DDIM][64];
    __shared__ float Vs[DDIM][64];
    for (int idx = threadIdx.x; idx < DDIM * 64; idx += 256) {
        int c = idx >> 6, i = idx & 63;
        Us[c][i] = u[(size_t)c * NPTS + I + i];
        Vs[c][i] = v[(size_t)c * NPTS + J + i];
    }
    __syncthreads();

    const int tx = threadIdx.x & 15;
    const int ty = threadIdx.x >> 4;
    float acc[4][4] = {};
#pragma unroll 8
    for (int k = 0; k < DDIM; ++k) {
        float4 a  = *(const float4*)&Us[k][ty * 4];
        float4 bb = *(const float4*)&Vs[k][tx * 4];
        acc[0][0] = fmaf(a.x, bb.x, acc[0][0]);
        acc[0][1] = fmaf(a.x, bb.y, acc[0][1]);
        acc[0][2] = fmaf(a.x, bb.z, acc[0][2]);
        acc[0][3] = fmaf(a.x, bb.w, acc[0][3]);
        acc[1][0] = fmaf(a.y, bb.x, acc[1][0]);
        acc[1][1] = fmaf(a.y, bb.y, acc[1][1]);
        acc[1][2] = fmaf(a.y, bb.z, acc[1][2]);
        acc[1][3] = fmaf(a.y, bb.w, acc[1][3]);
        acc[2][0] = fmaf(a.z, bb.x, acc[2][0]);
        acc[2][1] = fmaf(a.z, bb.y, acc[2][1]);
        acc[2][2] = fmaf(a.z, bb.z, acc[2][2]);
        acc[2][3] = fmaf(a.z, bb.w, acc[2][3]);
        acc[3][0] = fmaf(a.w, bb.x, acc[3][0]);
        acc[3][1] = fmaf(a.w, bb.y, acc[3][1]);
        acc[3][2] = fmaf(a.w, bb.z, acc[3][2]);
        acc[3][3] = fmaf(a.w, bb.w, acc[3][3]);
    }

    float* Cout = g_C + ((size_t)(b * 3 + which) << 24);
    float nvv[4];
#pragma unroll
    for (int q = 0; q < 4; ++q) nvv[q] = nv[J + tx * 4 + q];
#pragma unroll
    for (int ii = 0; ii < 4; ++ii) {
        int row = I + ty * 4 + ii;
        float nr = nu[row];
        float4 w;
        w.x = 0.5f * (nr + nvv[0]) - acc[ii][0];
        w.y = 0.5f * (nr + nvv[1]) - acc[ii][1];
        w.z = 0.5f * (nr + nvv[2]) - acc[ii][2];
        w.w = 0.5f * (nr + nvv[3]) - acc[ii][3];
        *(float4*)&Cout[(size_t)row * NPTS + J + tx * 4] = w;
    }
}

// ---------------------------------------------------------------------------
// Tile softmin pass. grid=(1024, 3, NB); 256 threads; 69120 B dyn smem.
//  mat 0 (xy): all 1024 tiles; row-LSE (h=hcol from g_ab) -> out0 partials,
//              col-LSE (h=hrow from f_ba) -> out1 partials.
//  mat 1 (xx): upper 528 tiles, h from f_aa both sides -> out2.
//  mat 2 (yy): upper 528 tiles, h from g_bb both sides -> out3.
// mode: 0 init (h=-12), 1/2 h from g_pot[src].
// ---------------------------------------------------------------------------
__global__ void __launch_bounds__(256) tile_kernel(float eps, int mode, int src) {
    const int mat = blockIdx.y;
    const int b = blockIdx.z;
    int si, sj;
    if (mat == 0) {
        si = blockIdx.x >> 5;
        sj = blockIdx.x & 31;
    } else {
        int t = blockIdx.x;
        if (t >= NUPPER) return;
        int rem = t; si = 0;
        while (rem >= NST - si) { rem -= NST - si; ++si; }
        sj = si + rem;
    }
    const float ie = 1.4426950408889634f / eps;

    extern __shared__ float sm[];
    float* tile = sm;                       // 128*129
    float* hrow = sm + TS * 129;            // 128
    float* hcol = hrow + TS;                // 128
    float* redb = hcol + TS;                // 512: rowm, rows, colm, cols

    const int tid = threadIdx.x;
    const int kA = (mat == 0) ? 0 : (mat == 1) ? 2 : 3;   // hrow (col-LSE h)
    const int kB = (mat == 0) ? 1 : kA;                   // hcol (row-LSE h)
    const float* __restrict__ potA = &g_pot[src][b][kA][0];
    const float* __restrict__ potB = &g_pot[src][b][kB][0];
    if (tid < TS) {
        float h = -12.0f;                                 // -log(4096)*log2e
        if (mode) h = fmaf(potA[si * TS + tid], ie, -12.0f);
        hrow[tid] = h;
    } else {
        int j = tid - TS;
        float h = -12.0f;
        if (mode) h = fmaf(potB[sj * TS + j], ie, -12.0f);
        hcol[j] = h;
    }

    // Vectorized tile load: LDG.128 (128 warp-LDGs/tile), scalar STS into the
    // odd-stride smem layout (16B-aligned vector STS impossible at stride 129).
    const float4* __restrict__ Cb4 = (const float4*)(
        g_C + ((size_t)(b * 3 + mat) << 24) + (size_t)si * TS * NPTS + sj * TS);
#pragma unroll
    for (int q = 0; q < 16; ++q) {
        int f = q * 256 + tid;              // 4096 float4s per tile
        int r = f >> 5, c4 = f & 31;        // 32 float4 per row
        float4 v = Cb4[(size_t)r * (NPTS / 4) + c4];
        float* d = &tile[r * 129 + c4 * 4];
        d[0] = v.x; d[1] = v.y; d[2] = v.z; d[3] = v.w;
    }
    __syncthreads();

    const int warp = tid >> 5, lane = tid & 31;

    // ---- row LSEs (exact 2-phase, add-merge sums) ----
    {
        float hc0 = hcol[lane], hc1 = hcol[lane + 32];
        float hc2 = hcol[lane + 64], hc3 = hcol[lane + 96];
#pragma unroll 2
        for (int rr = 0; rr < 16; ++rr) {
            int r = warp * 16 + rr;
            const float* tr = &tile[r * 129];
            float a0 = fmaf(tr[lane],      -ie, hc0);
            float a1 = fmaf(tr[lane + 32], -ie, hc1);
            float a2 = fmaf(tr[lane + 64], -ie, hc2);
            float a3 = fmaf(tr[lane + 96], -ie, hc3);
            float m = fmaxf(fmaxf(a0, a1), fmaxf(a2, a3));
#pragma unroll
            for (int o = 16; o; o >>= 1)
                m = fmaxf(m, __shfl_xor_sync(0xffffffffu, m, o));
            float s = ex2f(a0 - m) + ex2f(a1 - m) + ex2f(a2 - m) + ex2f(a3 - m);
#pragma unroll
            for (int o = 16; o; o >>= 1)
                s += __shfl_xor_sync(0xffffffffu, s, o);
            if (lane == 0) { redb[r] = m; redb[128 + r] = s; }
        }
    }
    // ---- col LSEs ----
    {
        float h0 = hrow[lane], h1 = hrow[lane + 32];
        float h2 = hrow[lane + 64], h3 = hrow[lane + 96];
#pragma unroll 2
        for (int cc = 0; cc < 16; ++cc) {
            int c = warp * 16 + cc;
            float a0 = fmaf(tile[lane * 129 + c],        -ie, h0);
            float a1 = fmaf(tile[(lane + 32) * 129 + c], -ie, h1);
            float a2 = fmaf(tile[(lane + 64) * 129 + c], -ie, h2);
            float a3 = fmaf(tile[(lane + 96) * 129 + c], -ie, h3);
            float m = fmaxf(fmaxf(a0, a1), fmaxf(a2, a3));
#pragma unroll
            for (int o = 16; o; o >>= 1)
                m = fmaxf(m, __shfl_xor_sync(0xffffffffu, m, o));
            float s = ex2f(a0 - m) + ex2f(a1 - m) + ex2f(a2 - m) + ex2f(a3 - m);
#pragma unroll
            for (int o = 16; o; o >>= 1)
                s += __shfl_xor_sync(0xffffffffu, s, o);
            if (lane == 0) { redb[256 + c] = m; redb[384 + c] = s; }
        }
    }
    __syncthreads();

    // ---- emit partials ----
    const int outR = (mat == 0) ? 0 : (mat == 1) ? 2 : 3;
    const int outC = (mat == 0) ? 1 : outR;
    if (tid < TS) {
        int grow = si * TS + tid;
        g_part[((size_t)(b * 4 + outR) * NPTS + grow) * NST + sj] =
            make_float2(redb[tid], redb[128 + tid]);
    } else if (mat == 0 || si != sj) {           // diagonal symmetric: skip cols
        int j = tid - TS;
        int gcol = sj * TS + j;
        g_part[((size_t)(b * 4 + outC) * NPTS + gcol) * NST + si] =
            make_float2(redb[256 + j], redb[384 + j]);
    }
}

// ---------------------------------------------------------------------------
// Combine: merge 32 (max,sum) partials per output row -> potential update.
// grid 8192 x 256 threads (warp per row). mode 1: average with old; 2: ->potF.
// ---------------------------------------------------------------------------
__global__ void __launch_bounds__(256) combine_kernel(float eps, int mode,
                                                      int src, int dst) {
    const int w = blockIdx.x * 8 + (threadIdx.x >> 5);     // 0..65535
    const int lane = threadIdx.x & 31;
    const int row = w & (NPTS - 1);
    const int out = (w >> 12) & 3;
    const int b = w >> 14;

    float2 p = g_part[((size_t)(b * 4 + out) * NPTS + row) * NST + lane];
    float m = p.x, s = p.y;
#pragma unroll
    for (int o = 16; o; o >>= 1) {
        float om = __shfl_xor_sync(0xffffffffu, m, o);
        float os = __shfl_xor_sync(0xffffffffu, s, o);
        float nm = fmaxf(m, om);
        s = fmaf(s, ex2f(m - nm), os * ex2f(om - nm));
        m = nm;
    }
    if (lane == 0) {
        float res = -eps * (m + log2f(s)) * 0.6931471805599453f;
        if (mode == 1) res = 0.5f * (g_pot[src][b][out][row] + res);
        if (mode == 2) g_potF[b][out][row] = res;
        else           g_pot[dst][b][out][row] = res;
    }
}

// ---------------------------------------------------------------------------
__global__ void __launch_bounds__(256) reduce_kernel(float* __restrict__ out) {
    __shared__ float sm[256];
    const float* p = &g_potF[0][0][0];
    float acc = 0.f;
    for (int idx = threadIdx.x; idx < NB * 4 * NPTS; idx += 256) {
        int mm = (idx / NPTS) & 3;
        float v = p[idx];
        acc += (mm < 2) ? v : -v;
    }
    sm[threadIdx.x] = acc;
    __syncthreads();
    for (int sft = 128; sft; sft >>= 1) {
        if (threadIdx.x < sft) sm[threadIdx.x] += sm[threadIdx.x + sft];
        __syncthreads();
    }
    if (threadIdx.x == 0) out[0] = sm[0] / ((float)NPTS * (float)NB);
}

// ---------------------------------------------------------------------------
extern "C" void kernel_launch(void* const* d_in, const int* in_sizes, int n_in,
                              void* d_out, int out_size) {
    const float* x = (const float*)d_in[0];
    const float* y = (const float*)d_in[1];

    float epsl[56];
    {
        double st = 2.0 * log(16.0);
        double sp = 2.0 * log(0.9);
        for (int k = 0; k < 55; ++k) epsl[k] = (float)exp(st + k * sp);
        epsl[55] = 0.0025f;
    }

    const int TSMEM = (TS * 129 + 2 * TS + 512) * 4;   // 69120 B
    cudaFuncSetAttribute(tile_kernel,
                         cudaFuncAttributeMaxDynamicSharedMemorySize, TSMEM);

    norm_kernel<<<(2 * NB * NPTS) / 256, 256>>>(x, y);
    cost_kernel<<<dim3(64, 64, 12), 256>>>(x, y);

    dim3 tg(NST * NST, 3, NB);
    // init at eps0 -> buffer 0
    tile_kernel<<<tg, 256, TSMEM>>>(epsl[0], 0, 0);
    combine_kernel<<<8192, 256>>>(epsl[0], 0, 0, 0);
    // 56 annealing steps: step s reads s&1, writes (s+1)&1
    for (int s = 0; s < 56; ++s) {
        tile_kernel<<<tg, 256, TSMEM>>>(epsl[s], 1, s & 1);
        combine_kernel<<<8192, 256>>>(epsl[s], 1, s & 1, (s + 1) & 1);
    }
    // final extrapolation at blur^2 from converged buffer 0 -> potF
    tile_kernel<<<tg, 256, TSMEM>>>(0.0025f, 2, 0);
    combine_kernel<<<8192, 256>>>(0.0025f, 2, 0, 0);

    reduce_kernel<<<1, 256>>>((float*)d_out);
}

// round 17
// speedup vs baseline: 1.1830x; 1.1830x over previous
#include <cuda_runtime.h>
#include <cuda_bf16.h>
#include <math.h>

// ============================================================================
// Sinkhorn divergence (geomloss 'sinkhorn', p=2, blur=0.05, scaling=0.9).
//
// Round-13: traffic-halved design (no C_yx; xx/yy upper-triangle only) with a
// REBUILT tile kernel after R12 post-mortem (258us/launch, latency+MUFU bound):
//  - row LSEs computed from REGISTERS during the tile load (warp w at load
//    iteration q holds the complete row 8q+w) -> no extra smem sweep,
//    1 EX2/entry, plain fmaxf/add butterflies only.
//  - tile stores a_row = hcol_j - C*ie at stride 132 (16B aligned, conflict-
//    free rows AND columns) so the column pass is add-only.
//  - column pass: lane-owned columns (128 cols x 2 half-segments), serial
//    2-pass per lane, zero shuffles, one smem half-merge. 1 EX2/entry.
// Per-step traffic: ~533 MB (vs 1024 MB in the 11347us baseline).
// ============================================================================

#define NPTS 4096
#define DDIM 64
#define NB   4
#define TS   128
#define NST  (NPTS / TS)               // 32 stripes
#define NUPPER (NST * (NST + 1) / 2)   // 528 upper tiles
#define TSTRIDE 132                    // smem row stride (16B aligned, ==4 mod 32)

// 12 matrices (xy, xx, yy per batch) x 64 MB = 768 MB
__device__ float g_C[(size_t)12 * NPTS * NPTS];
// partial (max,sum) per output row per stripe: [b][out][row][stripe]
// out: 0=f_ba(xy rows) 1=g_ab(xy cols) 2=f_aa(xx) 3=g_bb(yy)
__device__ float2 g_part[(size_t)NB * 4 * NPTS * NST];
// potentials ping-pong: [buf][b][{f_ba,g_ab,f_aa,g_bb}][NPTS]
__device__ float g_pot[2][NB][4][NPTS];
__device__ float g_potF[NB][4][NPTS];
__device__ float g_norm[2][NB][NPTS];

__device__ __forceinline__ float ex2f(float x) {
    float r;
    asm("ex2.approx.ftz.f32 %0, %1;" : "=f"(r) : "f"(x));
    return r;
}

// ---------------------------------------------------------------------------
__global__ void __launch_bounds__(256) norm_kernel(const float* __restrict__ x,
                                                   const float* __restrict__ y) {
    int t = blockIdx.x * 256 + threadIdx.x;
    int i = t & (NPTS - 1);
    int b = (t >> 12) & 3;
    int which = t >> 14;
    const float* p = (which ? y : x) + (size_t)b * DDIM * NPTS + i;
    float s = 0.f;
#pragma unroll
    for (int c = 0; c < DDIM; ++c) {
        float v = p[(size_t)c * NPTS];
        s = fmaf(v, v, s);
    }
    g_norm[which][b][i] = s;
}

// ---------------------------------------------------------------------------
// Cost matrices: mat 0: C(x,y); mat 1: C(x,x); mat 2: C(y,y).
// For mat>0 only upper 128-tiles (si<=sj) are written. grid=(64,64,12).
// ---------------------------------------------------------------------------
__global__ void __launch_bounds__(256) cost_kernel(const float* __restrict__ x,
                                                   const float* __restrict__ y) {
    const int which = blockIdx.z % 3;
    const int b = blockIdx.z / 3;
    if (which > 0 && (blockIdx.x >> 1) > (blockIdx.y >> 1)) return;  // upper only

    const float* u = (which == 2) ? y : x;
    const float* v = (which == 1) ? x : y;
    const float* nu = g_norm[(which == 2) ? 1 : 0][b];
    const float* nv = g_norm[(which == 1) ? 0 : 1][b];
    u += (size_t)b * DDIM * NPTS;
    v += (size_t)b * DDIM * NPTS;

    const int I = blockIdx.x * 64;
    const int J = blockIdx.y * 64;

    __shared__ float Us[DDIM][64];
    __shared__ float Vs[DDIM][64];
    for (int idx = threadIdx.x; idx < DDIM * 64; idx += 256) {
        int c = idx >> 6, i = idx & 63;
        Us[c][i] = u[(size_t)c * NPTS + I + i];
        Vs[c][i] = v[(size_t)c * NPTS + J + i];
    }
    __syncthreads();

    const int tx = threadIdx.x & 15;
    const int ty = threadIdx.x >> 4;
    float acc[4][4] = {};
#pragma unroll 8
    for (int k = 0; k < DDIM; ++k) {
        float4 a  = *(const float4*)&Us[k][ty * 4];
        float4 bb = *(const float4*)&Vs[k][tx * 4];
        acc[0][0] = fmaf(a.x, bb.x, acc[0][0]);
        acc[0][1] = fmaf(a.x, bb.y, acc[0][1]);
        acc[0][2] = fmaf(a.x, bb.z, acc[0][2]);
        acc[0][3] = fmaf(a.x, bb.w, acc[0][3]);
        acc[1][0] = fmaf(a.y, bb.x, acc[1][0]);
        acc[1][1] = fmaf(a.y, bb.y, acc[1][1]);
        acc[1][2] = fmaf(a.y, bb.z, acc[1][2]);
        acc[1][3] = fmaf(a.y, bb.w, acc[1][3]);
        acc[2][0] = fmaf(a.z, bb.x, acc[2][0]);
        acc[2][1] = fmaf(a.z, bb.y, acc[2][1]);
        acc[2][2] = fmaf(a.z, bb.z, acc[2][2]);
        acc[2][3] = fmaf(a.z, bb.w, acc[2][3]);
        acc[3][0] = fmaf(a.w, bb.x, acc[3][0]);
        acc[3][1] = fmaf(a.w, bb.y, acc[3][1]);
        acc[3][2] = fmaf(a.w, bb.z, acc[3][2]);
        acc[3][3] = fmaf(a.w, bb.w, acc[3][3]);
    }

    float* Cout = g_C + ((size_t)(b * 3 + which) << 24);
    float nvv[4];
#pragma unroll
    for (int q = 0; q < 4; ++q) nvv[q] = nv[J + tx * 4 + q];
#pragma unroll
    for (int ii = 0; ii < 4; ++ii) {
        int row = I + ty * 4 + ii;
        float nr = nu[row];
        float4 w;
        w.x = 0.5f * (nr + nvv[0]) - acc[ii][0];
        w.y = 0.5f * (nr + nvv[1]) - acc[ii][1];
        w.z = 0.5f * (nr + nvv[2]) - acc[ii][2];
        w.w = 0.5f * (nr + nvv[3]) - acc[ii][3];
        *(float4*)&Cout[(size_t)row * NPTS + J + tx * 4] = w;
    }
}

// ---------------------------------------------------------------------------
// Tile softmin pass v2. grid=(1024, 3, NB); 256 threads.
//  mat 0 (xy): all 1024 tiles; row-LSE (h=hcol from g_ab) -> out0 partials,
//              col-LSE (h=hrow from f_ba) -> out1 partials.
//  mat 1 (xx): upper 528 tiles, h from f_aa both sides -> out2.
//  mat 2 (yy): upper 528 tiles, h from g_bb both sides -> out3.
// mode: 0 init (h=-12), 1/2 h from g_pot[src].
// smem: tile 128*132 floats + hcol 128 + hrow 128 + redb 768 = 71680 B.
// ---------------------------------------------------------------------------
__global__ void __launch_bounds__(256) tile_kernel(float eps, int mode, int src) {
    const int mat = blockIdx.y;
    const int b = blockIdx.z;
    int si, sj;
    if (mat == 0) {
        si = blockIdx.x >> 5;
        sj = blockIdx.x & 31;
    } else {
        int t = blockIdx.x;
        if (t >= NUPPER) return;
        int rem = t; si = 0;
        while (rem >= NST - si) { rem -= NST - si; ++si; }
        sj = si + rem;
    }
    const float ie = 1.4426950408889634f / eps;

    extern __shared__ float sm[];
    float* tile = sm;                         // 128*132 (stores a_row values)
    float* hcol = sm + TS * TSTRIDE;          // 128
    float* hrow = hcol + TS;                  // 128
    float* redb = hrow + TS;                  // 768:
    // [0:128) row m | [128:256) row s | [256:384) col m | [384:512) col s
    // [512:640) col half0 m | [640:768) col half0 s

    const int tid = threadIdx.x;
    const int kA = (mat == 0) ? 0 : (mat == 1) ? 2 : 3;   // hrow (col-LSE h)
    const int kB = (mat == 0) ? 1 : kA;                   // hcol (row-LSE h)
    const float* __restrict__ potA = &g_pot[src][b][kA][0];
    const float* __restrict__ potB = &g_pot[src][b][kB][0];
    if (tid < TS) {
        hrow[tid] = mode ? fmaf(potA[si * TS + tid], ie, -12.0f) : -12.0f;
    } else {
        int j = tid - TS;
        hcol[j] = mode ? fmaf(potB[sj * TS + j], ie, -12.0f) : -12.0f;
    }
    __syncthreads();

    const int warp = tid >> 5, lane = tid & 31;

    // ---- fused load + row LSEs (warp w holds full row 8q+w at iteration q) --
    const float4 hc = *(const float4*)&hcol[lane * 4];
    const float4* __restrict__ Cb4 = (const float4*)(
        g_C + ((size_t)(b * 3 + mat) << 24) + (size_t)si * TS * NPTS + sj * TS);
#pragma unroll 4
    for (int q = 0; q < 16; ++q) {
        const int r = q * 8 + warp;
        float4 v = Cb4[(size_t)r * (NPTS / 4) + lane];
        float a0 = fmaf(v.x, -ie, hc.x);
        float a1 = fmaf(v.y, -ie, hc.y);
        float a2 = fmaf(v.z, -ie, hc.z);
        float a3 = fmaf(v.w, -ie, hc.w);
        *(float4*)&tile[r * TSTRIDE + lane * 4] = make_float4(a0, a1, a2, a3);
        // max butterfly (pure fmaxf)
        float m = fmaxf(fmaxf(a0, a1), fmaxf(a2, a3));
#pragma unroll
        for (int o = 16; o; o >>= 1)
            m = fmaxf(m, __shfl_xor_sync(0xffffffffu, m, o));
        // sum butterfly (pure adds)
        float s = ex2f(a0 - m) + ex2f(a1 - m) + ex2f(a2 - m) + ex2f(a3 - m);
#pragma unroll
        for (int o = 16; o; o >>= 1)
            s += __shfl_xor_sync(0xffffffffu, s, o);
        if (lane == 0) { redb[r] = m; redb[128 + r] = s; }
    }
    __syncthreads();

    // ---- col LSEs: lane owns column c, half-segment of 64 rows, 2-pass ----
    {
        const int c = tid & 127;
        const int h0 = (tid >> 7) * 64;       // 0 or 64
        const float hcc = hcol[c];
        float mm = -1e30f;
#pragma unroll 8
        for (int i = 0; i < 64; i += 4) {
            float4 hr = *(const float4*)&hrow[h0 + i];   // warp-broadcast
            float d0 = hr.x - hcc, d1 = hr.y - hcc;
            float d2 = hr.z - hcc, d3 = hr.w - hcc;
            mm = fmaxf(mm, tile[(h0 + i + 0) * TSTRIDE + c] + d0);
            mm = fmaxf(mm, tile[(h0 + i + 1) * TSTRIDE + c] + d1);
            mm = fmaxf(mm, tile[(h0 + i + 2) * TSTRIDE + c] + d2);
            mm = fmaxf(mm, tile[(h0 + i + 3) * TSTRIDE + c] + d3);
        }
        float ss = 0.f;
#pragma unroll 8
        for (int i = 0; i < 64; i += 4) {
            float4 hr = *(const float4*)&hrow[h0 + i];
            float d0 = hr.x - hcc - mm, d1 = hr.y - hcc - mm;
            float d2 = hr.z - hcc - mm, d3 = hr.w - hcc - mm;
            ss += ex2f(tile[(h0 + i + 0) * TSTRIDE + c] + d0)
                + ex2f(tile[(h0 + i + 1) * TSTRIDE + c] + d1)
                + ex2f(tile[(h0 + i + 2) * TSTRIDE + c] + d2)
                + ex2f(tile[(h0 + i + 3) * TSTRIDE + c] + d3);
        }
        if (tid < 128) { redb[512 + c] = mm; redb[640 + c] = ss; }
        __syncthreads();
        if (tid >= 128) {                      // merge half0 (smem) + half1 (regs)
            float m0 = redb[512 + c], s0 = redb[640 + c];
            float M = fmaxf(mm, m0);
            float S = fmaf(ss, ex2f(mm - M), s0 * ex2f(m0 - M));
            redb[256 + c] = M; redb[384 + c] = S;
        }
    }
    __syncthreads();

    // ---- emit partials ----
    const int outR = (mat == 0) ? 0 : (mat == 1) ? 2 : 3;
    const int outC = (mat == 0) ? 1 : outR;
    if (tid < TS) {
        int grow = si * TS + tid;
        g_part[((size_t)(b * 4 + outR) * NPTS + grow) * NST + sj] =
            make_float2(redb[tid], redb[128 + tid]);
    } else if (mat == 0 || si != sj) {         // diagonal symmetric: skip cols
        int j = tid - TS;
        int gcol = sj * TS + j;
        g_part[((size_t)(b * 4 + outC) * NPTS + gcol) * NST + si] =
            make_float2(redb[256 + j], redb[384 + j]);
    }
}

// ---------------------------------------------------------------------------
// Combine: merge 32 (max,sum) partials per output row -> potential update.
// grid 8192 x 256 threads (warp per row). mode 1: average with old; 2: ->potF.
// ---------------------------------------------------------------------------
__global__ void __launch_bounds__(256) combine_kernel(float eps, int mode,
                                                      int src, int dst) {
    const int w = blockIdx.x * 8 + (threadIdx.x >> 5);     // 0..65535
    const int lane = threadIdx.x & 31;
    const int row = w & (NPTS - 1);
    const int out = (w >> 12) & 3;
    const int b = w >> 14;

    float2 p = g_part[((size_t)(b * 4 + out) * NPTS + row) * NST + lane];
    float m = p.x, s = p.y;
#pragma unroll
    for (int o = 16; o; o >>= 1) {
        float om = __shfl_xor_sync(0xffffffffu, m, o);
        float os = __shfl_xor_sync(0xffffffffu, s, o);
        float nm = fmaxf(m, om);
        s = fmaf(s, ex2f(m - nm), os * ex2f(om - nm));
        m = nm;
    }
    if (lane == 0) {
        float res = -eps * (m + log2f(s)) * 0.6931471805599453f;
        if (mode == 1) res = 0.5f * (g_pot[src][b][out][row] + res);
        if (mode == 2) g_potF[b][out][row] = res;
        else           g_pot[dst][b][out][row] = res;
    }
}

// ---------------------------------------------------------------------------
__global__ void __launch_bounds__(256) reduce_kernel(float* __restrict__ out) {
    __shared__ float sm[256];
    const float* p = &g_potF[0][0][0];
    float acc = 0.f;
    for (int idx = threadIdx.x; idx < NB * 4 * NPTS; idx += 256) {
        int mm = (idx / NPTS) & 3;
        float v = p[idx];
        acc += (mm < 2) ? v : -v;
    }
    sm[threadIdx.x] = acc;
    __syncthreads();
    for (int sft = 128; sft; sft >>= 1) {
        if (threadIdx.x < sft) sm[threadIdx.x] += sm[threadIdx.x + sft];
        __syncthreads();
    }
    if (threadIdx.x == 0) out[0] = sm[0] / ((float)NPTS * (float)NB);
}

// ---------------------------------------------------------------------------
extern "C" void kernel_launch(void* const* d_in, const int* in_sizes, int n_in,
                              void* d_out, int out_size) {
    const float* x = (const float*)d_in[0];
    const float* y = (const float*)d_in[1];

    float epsl[56];
    {
        double st = 2.0 * log(16.0);
        double sp = 2.0 * log(0.9);
        for (int k = 0; k < 55; ++k) epsl[k] = (float)exp(st + k * sp);
        epsl[55] = 0.0025f;
    }

    const int TSMEM = (TS * TSTRIDE + 2 * TS + 768) * 4;   // 71680 B
    cudaFuncSetAttribute(tile_kernel,
                         cudaFuncAttributeMaxDynamicSharedMemorySize, TSMEM);

    norm_kernel<<<(2 * NB * NPTS) / 256, 256>>>(x, y);
    cost_kernel<<<dim3(64, 64, 12), 256>>>(x, y);

    dim3 tg(NST * NST, 3, NB);
    // init at eps0 -> buffer 0
    tile_kernel<<<tg, 256, TSMEM>>>(epsl[0], 0, 0);
    combine_kernel<<<8192, 256>>>(epsl[0], 0, 0, 0);
    // 56 annealing steps: step s reads s&1, writes (s+1)&1
    for (int s = 0; s < 56; ++s) {
        tile_kernel<<<tg, 256, TSMEM>>>(epsl[s], 1, s & 1);
        combine_kernel<<<8192, 256>>>(epsl[s], 1, s & 1, (s + 1) & 1);
    }
    // final extrapolation at blur^2 from converged buffer 0 -> potF
    tile_kernel<<<tg, 256, TSMEM>>>(0.0025f, 2, 0);
    combine_kernel<<<8192, 256>>>(0.0025f, 2, 0, 0);

    reduce_kernel<<<1, 256>>>((float*)d_out);
}